// round 7
// baseline (speedup 1.0000x reference)
#include <cuda_runtime.h>
#include <cuda_fp16.h>

#define B_   8
#define H_   8
#define QS_  64
#define KS_  512
#define A_   64
#define DH_  64
#define KC_  64
#define NCH_ 8      // total k-chunks
#define CPC_ 2      // chunks per CTA
#define NP_  4      // partials per (b,h)
#define QD_  512
#define KD_  512

typedef unsigned long long ull;

__device__ float g_pout[B_*H_*NP_*QS_*DH_];   // 4 MB
__device__ float g_Sx[B_*H_*NP_*QS_];
__device__ int   g_cnt[B_*H_];                // zero-init; self-resetting

__device__ __forceinline__ float fast_tanh(float v) {
    float y; asm("tanh.approx.f32 %0, %1;" : "=f"(y) : "f"(v)); return y;
}
__device__ __forceinline__ ull pk2(float x, float y) {
    ull r; asm("mov.b64 %0, {%1, %2};" : "=l"(r) : "f"(x), "f"(y)); return r;
}
__device__ __forceinline__ float2 upk2(ull v) {
    float2 r; asm("mov.b64 {%0, %1}, %2;" : "=f"(r.x), "=f"(r.y) : "l"(v)); return r;
}
__device__ __forceinline__ ull ffma2(ull a, ull b, ull c) {
    ull d; asm("fma.rn.f32x2 %0, %1, %2, %3;" : "=l"(d) : "l"(a), "l"(b), "l"(c)); return d;
}

// ---------------- smem layout (bytes), total 71168 -> 3 CTAs/SM ----------------
//  s_xv   @0      f32[64][68] 17408   (query in ph1; x chunk (=K=V) per chunk)
//  s_kph  @17408  half[64][72] 9216   ([a][k])
//  s_qph  @26624  half[64][72] 9216   ([a][q], persists across chunks)
//  s_Wst  @35840  f32[64][68] 17408   (Wq, then Wk persists across chunks)
//  s_p    @53248  f32[64][68] 17408
//  s_misc @70656  bias f32[64]; w2 f32[64] @70912; flag int @71164
#define SMF_BYTES 71168

// 64 rows x 64 a projection GEMM: s_in[r*68+d], s_w[a*68+d] -> s_out[a*72+r] (half)
__device__ __forceinline__ void proj_gemm(
    const float* __restrict__ s_in, const float* __restrict__ s_w,
    __half* __restrict__ s_out, const float* __restrict__ s_bias,
    int tx, int ty)
{
    ull acc2[4][4];
#pragma unroll
    for (int i = 0; i < 4; i++)
#pragma unroll
        for (int j = 0; j < 4; j++) acc2[i][j] = 0ULL;

#pragma unroll
    for (int d4 = 0; d4 < 16; d4++) {
        ull wv[4][2];
#pragma unroll
        for (int j = 0; j < 4; j++) {
            float4 v = *(const float4*)&s_w[(tx + 16 * j) * 68 + d4 * 4];
            wv[j][0] = pk2(v.x, v.y); wv[j][1] = pk2(v.z, v.w);
        }
#pragma unroll
        for (int i = 0; i < 4; i++) {
            float4 v = *(const float4*)&s_in[(ty * 4 + i) * 68 + d4 * 4];
            ull r0 = pk2(v.x, v.y), r1 = pk2(v.z, v.w);
#pragma unroll
            for (int j = 0; j < 4; j++) {
                acc2[i][j] = ffma2(r0, wv[j][0], acc2[i][j]);
                acc2[i][j] = ffma2(r1, wv[j][1], acc2[i][j]);
            }
        }
    }
#pragma unroll
    for (int i = 0; i < 4; i++)
#pragma unroll
        for (int j = 0; j < 4; j++) {
            float2 p = upk2(acc2[i][j]);
            float v = p.x + p.y + (s_bias ? s_bias[tx + 16 * j] : 0.f);
            s_out[(tx + 16 * j) * 72 + ty * 4 + i] = __float2half_rn(v);
        }
}

__global__ void __launch_bounds__(256, 3) fused_kernel(
    const float* __restrict__ x, const float* __restrict__ query,
    const float* __restrict__ W, const float* __restrict__ bias,
    const float* __restrict__ w2, const unsigned char* __restrict__ mask,
    float* __restrict__ out)
{
    extern __shared__ char sm[];
    float*  s_xv  = (float*)(sm);
    __half* s_kph = (__half*)(sm + 17408);
    __half* s_qph = (__half*)(sm + 26624);
    float*  s_Wst = (float*)(sm + 35840);
    float*  s_p   = (float*)(sm + 53248);
    float*  s_bias= (float*)(sm + 70656);
    float*  s_w2  = (float*)(sm + 70912);
    int*    s_last= (int*)(sm + 71164);

    const int kcp = blockIdx.x, h = blockIdx.y, b = blockIdx.z;
    const int tid = threadIdx.x;
    const int tx = tid & 15, ty = tid >> 4;
    const int bh = b * H_ + h;
    const int kc0 = kcp * CPC_;

    if (tid < 64) { s_bias[tid] = bias[tid]; s_w2[tid] = w2[tid]; }

    // ---- phase 1: stage query + Wq ----
#pragma unroll
    for (int i = 0; i < 4; i++) {
        int idx = tid + 256 * i; int q = idx >> 4, d4 = idx & 15;
        *(float4*)&s_xv[q * 68 + d4 * 4] =
            *(const float4*)&query[(size_t)(b * QS_ + q) * QD_ + h * DH_ + d4 * 4];
    }
#pragma unroll
    for (int i = 0; i < 4; i++) {
        int idx = tid + 256 * i; int a = idx >> 4, d4 = idx & 15;
        *(float4*)&s_Wst[a * 68 + d4 * 4] = *(const float4*)&W[a * 128 + 64 + d4 * 4];
    }
    __syncthreads();

    // ---- qp projection -> s_qph[a][q]  (persists) ----
    proj_gemm(s_xv, s_Wst, s_qph, s_bias, tx, ty);
    __syncthreads();

    // ---- stage Wk (persists) + x chunk 0 ----
#pragma unroll
    for (int i = 0; i < 4; i++) {
        int idx = tid + 256 * i; int a = idx >> 4, d4 = idx & 15;
        *(float4*)&s_Wst[a * 68 + d4 * 4] = *(const float4*)&W[a * 128 + d4 * 4];
    }
#pragma unroll
    for (int i = 0; i < 4; i++) {
        int idx = tid + 256 * i; int k = idx >> 4, d4 = idx & 15;
        *(float4*)&s_xv[k * 68 + d4 * 4] =
            *(const float4*)&x[((size_t)b * KS_ + kc0 * KC_ + k) * KD_ + h * DH_ + d4 * 4];
    }
    __syncthreads();

    // cross-chunk accumulators
    float rowsum[4] = {0.f, 0.f, 0.f, 0.f};     // rows ty*4+j (valid in all 16 tx lanes)
    ull o2[4][2];
#pragma unroll
    for (int j = 0; j < 4; j++) { o2[j][0] = 0ULL; o2[j][1] = 0ULL; }

    const int q0 = ty * 4, k0 = tx * 4;
    const int txd = tid & 15, tyq = tid >> 4;
    const int d0 = txd * 4, q0b = tyq * 4;

#pragma unroll
    for (int c = 0; c < CPC_; c++) {
        // ---- kp projection -> s_kph[a][k] ----
        proj_gemm(s_xv, s_Wst, s_kph, (const float*)0, tx, ty);
        __syncthreads();

        // ---- tanh scores + unnormalized exp (no max: |score| <= sum|w2| small) ----
        float acc[4][4];
#pragma unroll
        for (int j = 0; j < 4; j++)
#pragma unroll
            for (int i = 0; i < 4; i++) acc[j][i] = 0.f;

#pragma unroll 4
        for (int a = 0; a < A_; a++) {
            uint2 qr = *(const uint2*)&s_qph[a * 72 + q0];
            uint2 kr = *(const uint2*)&s_kph[a * 72 + k0];
            float2 qf0 = __half22float2(((const __half2*)&qr)[0]);
            float2 qf1 = __half22float2(((const __half2*)&qr)[1]);
            float2 kf0 = __half22float2(((const __half2*)&kr)[0]);
            float2 kf1 = __half22float2(((const __half2*)&kr)[1]);
            float w2a = s_w2[a];
            float qs[4] = {qf0.x, qf0.y, qf1.x, qf1.y};
            float ks[4] = {kf0.x, kf0.y, kf1.x, kf1.y};
#pragma unroll
            for (int j = 0; j < 4; j++)
#pragma unroll
                for (int i = 0; i < 4; i++)
                    acc[j][i] += w2a * fast_tanh(qs[j] + ks[i]);
        }

        {
            uchar4 mk4 = *(const uchar4*)&mask[b * KS_ + (kc0 + c) * KC_ + k0];
            unsigned char mk[4] = {mk4.x, mk4.y, mk4.z, mk4.w};
#pragma unroll
            for (int j = 0; j < 4; j++) {
                float s = 0.f;
#pragma unroll
                for (int i = 0; i < 4; i++) {
                    float p = mk[i] ? 0.f : __expf(acc[j][i]);
                    acc[j][i] = p;
                    s += p;
                }
#pragma unroll
                for (int o = 8; o; o >>= 1) s += __shfl_xor_sync(0xffffffffu, s, o);
                rowsum[j] += s;
            }
#pragma unroll
            for (int j = 0; j < 4; j++)
                *(float4*)&s_p[(q0 + j) * 68 + k0] =
                    make_float4(acc[j][0], acc[j][1], acc[j][2], acc[j][3]);
        }
        __syncthreads();

        // ---- pV accumulate (4q x 4d per thread), V = s_xv of this chunk ----
#pragma unroll 4
        for (int k = 0; k < KC_; k++) {
            float4 v = *(float4*)&s_xv[k * 68 + d0];
            ull v0 = pk2(v.x, v.y), v1 = pk2(v.z, v.w);
#pragma unroll
            for (int j = 0; j < 4; j++) {
                float p = s_p[(q0b + j) * 68 + k];
                ull p2 = pk2(p, p);
                o2[j][0] = ffma2(p2, v0, o2[j][0]);
                o2[j][1] = ffma2(p2, v1, o2[j][1]);
            }
        }

        // ---- stage next x chunk ----
        if (c + 1 < CPC_) {
            __syncthreads();   // pV reads of s_xv complete
#pragma unroll
            for (int i = 0; i < 4; i++) {
                int idx = tid + 256 * i; int k = idx >> 4, d4 = idx & 15;
                *(float4*)&s_xv[k * 68 + d4 * 4] =
                    *(const float4*)&x[((size_t)b * KS_ + (kc0 + c + 1) * KC_ + k) * KD_ + h * DH_ + d4 * 4];
            }
            __syncthreads();
        }
    }

    // ---- write partials ----
    const int pp = bh * NP_ + kcp;
#pragma unroll
    for (int j = 0; j < 4; j++) {
        float2 a0 = upk2(o2[j][0]), a1 = upk2(o2[j][1]);
        *(float4*)&g_pout[(size_t)(pp * QS_ + q0b + j) * DH_ + d0] =
            make_float4(a0.x, a0.y, a1.x, a1.y);
    }
    if (tx == 0) {
#pragma unroll
        for (int j = 0; j < 4; j++)
            g_Sx[pp * QS_ + q0 + j] = rowsum[j];
    }

    // ---- last CTA per (b,h) merges ----
    __threadfence();
    if (tid == 0) {
        int old = atomicAdd(&g_cnt[bh], 1);
        *s_last = (old == NP_ - 1);
    }
    __syncthreads();
    if (*s_last) {
        __threadfence();
        const int qrow = tid >> 2, l4 = tid & 3;
        float St = 0.f;
#pragma unroll
        for (int p = 0; p < NP_; p++) St += g_Sx[(bh * NP_ + p) * QS_ + qrow];
        float inv = 1.f / St;
#pragma unroll
        for (int j = 0; j < 4; j++) {
            int dd = (l4 * 4 + j) * 4;
            float4 a = make_float4(0.f, 0.f, 0.f, 0.f);
#pragma unroll
            for (int p = 0; p < NP_; p++) {
                float4 v = *(const float4*)&g_pout[(size_t)((bh * NP_ + p) * QS_ + qrow) * DH_ + dd];
                a.x += v.x; a.y += v.y; a.z += v.z; a.w += v.w;
            }
            a.x *= inv; a.y *= inv; a.z *= inv; a.w *= inv;
            *(float4*)&out[(size_t)(b * QS_ + qrow) * QD_ + h * DH_ + dd] = a;
        }
        if (tid == 0) g_cnt[bh] = 0;   // reset for next (graph-replayed) launch
    }
}

// ---------------- launch ----------------
extern "C" void kernel_launch(void* const* d_in, const int* in_sizes, int n_in,
                              void* d_out, int out_size) {
    const float* x     = (const float*)d_in[0];
    const float* query = (const float*)d_in[1];
    const float* W     = (const float*)d_in[2];
    const float* bias  = (const float*)d_in[3];
    const float* w2    = (const float*)d_in[4];
    const unsigned char* mask = (const unsigned char*)d_in[5];
    float* out = (float*)d_out;

    cudaFuncSetAttribute(fused_kernel, cudaFuncAttributeMaxDynamicSharedMemorySize, SMF_BYTES);

    fused_kernel<<<dim3(NP_, H_, B_), 256, SMF_BYTES>>>(x, query, W, bias, w2, mask, out);
}